// round 7
// baseline (speedup 1.0000x reference)
#include <cuda_runtime.h>
#include <cuda_bf16.h>
#include <cstdint>

#define N_NODES 100000
#define N_EDGES 1600000
#define D 128
#define SCAN_BLK 1024
#define N_SCAN_BLKS ((N_NODES + SCAN_BLK - 1) / SCAN_BLK)   // 98

// ---------------- device-global scratch ----------------
__device__ float g_h[(size_t)N_NODES * D];   // dinv[n] * (x @ W)[n]
__device__ float g_dinv[N_NODES];
__device__ int   g_degs[N_NODES];
__device__ int   g_cntd[N_NODES];
__device__ int   g_cur[N_NODES];             // bucket cursors (relative, zero-init)
__device__ int   g_offp[N_NODES];            // per-block exclusive scan partials
__device__ int   g_bsums[SCAN_BLK];          // block sums -> exclusive after scan2
__device__ int   g_esrc[N_EDGES];

__device__ __forceinline__ uint32_t smem_u32(const void* p) {
    uint32_t a;
    asm("{ .reg .u64 t; cvta.to.shared.u64 t, %1; cvt.u32.u64 %0, t; }" : "=r"(a) : "l"(p));
    return a;
}
__device__ __forceinline__ void ldm4(uint32_t* r, uint32_t addr) {
    asm volatile("ldmatrix.sync.aligned.m8n8.x4.shared.b16 {%0,%1,%2,%3}, [%4];"
                 : "=r"(r[0]), "=r"(r[1]), "=r"(r[2]), "=r"(r[3]) : "r"(addr));
}
__device__ __forceinline__ void mma_bf16(float* c, const uint32_t* a, uint32_t b0, uint32_t b1) {
    asm volatile("mma.sync.aligned.m16n8k16.row.col.f32.bf16.bf16.f32 "
                 "{%0,%1,%2,%3}, {%4,%5,%6,%7}, {%8,%9}, {%0,%1,%2,%3};"
                 : "+f"(c[0]), "+f"(c[1]), "+f"(c[2]), "+f"(c[3])
                 : "r"(a[0]), "r"(a[1]), "r"(a[2]), "r"(a[3]), "r"(b0), "r"(b1));
}

// ---------- 1) zero int scratch ----------
__global__ void k_zero() {
    int i = blockIdx.x * blockDim.x + threadIdx.x;
    if (i < N_NODES) { g_degs[i] = 0; g_cntd[i] = 0; g_cur[i] = 0; }
}

// ---------- 2) histograms (2 edges/thread via int2) ----------
__global__ void k_count(const int* __restrict__ ei) {
    int t = blockIdx.x * blockDim.x + threadIdx.x;
    if (t < N_EDGES / 2) {
        int2 s = ((const int2*)ei)[t];
        int2 d = ((const int2*)(ei + N_EDGES))[t];
        atomicAdd(&g_degs[s.x], 1); atomicAdd(&g_degs[s.y], 1);
        atomicAdd(&g_cntd[d.x], 1); atomicAdd(&g_cntd[d.y], 1);
    }
}

// ---------- 3) dinv ----------
__global__ void k_dinv() {
    int i = blockIdx.x * blockDim.x + threadIdx.x;
    if (i < N_NODES) {
        int d = g_degs[i];
        g_dinv[i] = (d > 0) ? rsqrtf((float)d) : 0.0f;
    }
}

// ---------- 4) exclusive scan of g_cntd: offp (in-block) + bsums (cross-block) ----------
__global__ void k_scan1() {
    __shared__ int s[SCAN_BLK];
    int tid = threadIdx.x;
    int i = blockIdx.x * SCAN_BLK + tid;
    int v = (i < N_NODES) ? g_cntd[i] : 0;
    s[tid] = v;
    __syncthreads();
    #pragma unroll
    for (int o = 1; o < SCAN_BLK; o <<= 1) {
        int t = (tid >= o) ? s[tid - o] : 0;
        __syncthreads();
        s[tid] += t;
        __syncthreads();
    }
    if (i < N_NODES) g_offp[i] = s[tid] - v;
    if (tid == SCAN_BLK - 1) g_bsums[blockIdx.x] = s[tid];
}
__global__ void k_scan2() {
    __shared__ int s[SCAN_BLK];
    int tid = threadIdx.x;
    int v = (tid < N_SCAN_BLKS) ? g_bsums[tid] : 0;
    s[tid] = v;
    __syncthreads();
    #pragma unroll
    for (int o = 1; o < SCAN_BLK; o <<= 1) {
        int t = (tid >= o) ? s[tid - o] : 0;
        __syncthreads();
        s[tid] += t;
        __syncthreads();
    }
    if (tid < N_SCAN_BLKS) g_bsums[tid] = s[tid] - v;
}

// ---------- 5) bucket edges by dst (offset computed inline; cursor is relative) ----------
__global__ void k_bucket(const int* __restrict__ ei) {
    int t = blockIdx.x * blockDim.x + threadIdx.x;
    if (t < N_EDGES / 2) {
        int2 s = ((const int2*)ei)[t];
        int2 d = ((const int2*)(ei + N_EDGES))[t];
        int p0 = atomicAdd(&g_cur[d.x], 1);
        g_esrc[g_offp[d.x] + g_bsums[d.x >> 10] + p0] = s.x;
        int p1 = atomicAdd(&g_cur[d.y], 1);
        g_esrc[g_offp[d.y] + g_bsums[d.y >> 10] + p1] = s.y;
    }
}

// ---------- 6) HMMA bf16x3 GEMM: g_h = dinv .* (x @ W) ----------
#define KS 136                       // smem row stride in halves
#define ROWB (KS * 2)                // 272 bytes
#define OFF_AH 0
#define OFF_AL (256 * ROWB)
#define OFF_BH (2 * 256 * ROWB)
#define OFF_BL (OFF_BH + 128 * ROWB)
#define SM_TOTAL (OFF_BL + 128 * ROWB)  // 208896 B

__global__ void __launch_bounds__(512, 1)
k_gemm(const float* __restrict__ x, const float* __restrict__ w) {
    extern __shared__ __align__(16) char smem[];
    const int tid = threadIdx.x;
    const int lane = tid & 31;
    const int wid = tid >> 5;
    const int row0 = blockIdx.x * 256;

    // ---- stage A: 256 rows x 128 cols, hi+lo bf16 ----
    #pragma unroll
    for (int i = tid; i < 4096; i += 512) {
        int r = i >> 4, c8 = i & 15;
        int gr = row0 + r;
        float4 v0 = make_float4(0.f, 0.f, 0.f, 0.f), v1 = v0;
        if (gr < N_NODES) {
            const float4* xp = (const float4*)(x + (size_t)gr * D + c8 * 8);
            v0 = xp[0]; v1 = xp[1];
        }
        float f[8] = {v0.x, v0.y, v0.z, v0.w, v1.x, v1.y, v1.z, v1.w};
        uint32_t hi[4], lo[4];
        #pragma unroll
        for (int j = 0; j < 4; j++) {
            float a = f[2 * j], b = f[2 * j + 1];
            __nv_bfloat16 ha = __float2bfloat16_rn(a), hb = __float2bfloat16_rn(b);
            float la = a - __bfloat162float(ha), lb = b - __bfloat162float(hb);
            __nv_bfloat16 hla = __float2bfloat16_rn(la), hlb = __float2bfloat16_rn(lb);
            hi[j] = ((uint32_t)__bfloat16_as_ushort(hb) << 16) | __bfloat16_as_ushort(ha);
            lo[j] = ((uint32_t)__bfloat16_as_ushort(hlb) << 16) | __bfloat16_as_ushort(hla);
        }
        char* pa = smem + r * ROWB + c8 * 16;
        *(uint4*)(pa + OFF_AH) = make_uint4(hi[0], hi[1], hi[2], hi[3]);
        *(uint4*)(pa + OFF_AL) = make_uint4(lo[0], lo[1], lo[2], lo[3]);
    }

    // ---- stage B = W^T: [n][k], hi+lo bf16 ----
    #pragma unroll
    for (int i = tid; i < 16384; i += 512) {
        int k = i >> 7, n = i & 127;
        float wv = w[i];                      // w[k*128 + n], coalesced
        __nv_bfloat16 hb = __float2bfloat16_rn(wv);
        __nv_bfloat16 lb = __float2bfloat16_rn(wv - __bfloat162float(hb));
        int off = n * ROWB + k * 2;
        *(__nv_bfloat16*)(smem + OFF_BH + off) = hb;
        *(__nv_bfloat16*)(smem + OFF_BL + off) = lb;
    }
    __syncthreads();

    const uint32_t sbase = smem_u32(smem);
    const int wm = (wid >> 1) * 32;
    const int wn = (wid & 1) * 64;

    const uint32_t aoff = sbase + (uint32_t)((wm + (lane & 15)) * ROWB + (lane >> 4) * 16);
    const uint32_t boff = sbase + (uint32_t)((wn + (lane & 15)) * ROWB + (lane >> 4) * 16);

    float acc[2][8][4];
    #pragma unroll
    for (int a = 0; a < 2; a++)
        #pragma unroll
        for (int b = 0; b < 8; b++)
            #pragma unroll
            for (int c = 0; c < 4; c++) acc[a][b][c] = 0.0f;

    #pragma unroll
    for (int ks = 0; ks < 8; ks++) {
        const uint32_t kb = ks * 32;
        uint32_t ah[2][4], al[2][4];
        #pragma unroll
        for (int mi = 0; mi < 2; mi++) {
            ldm4(ah[mi], aoff + OFF_AH + mi * 16 * ROWB + kb);
            ldm4(al[mi], aoff + OFF_AL + mi * 16 * ROWB + kb);
        }
        #pragma unroll
        for (int pj = 0; pj < 4; pj++) {
            uint32_t bh[4], bl[4];
            ldm4(bh, boff + OFF_BH + pj * 16 * ROWB + kb);
            ldm4(bl, boff + OFF_BL + pj * 16 * ROWB + kb);
            #pragma unroll
            for (int mi = 0; mi < 2; mi++) {
                mma_bf16(acc[mi][pj * 2],     ah[mi], bh[0], bh[2]);
                mma_bf16(acc[mi][pj * 2],     ah[mi], bl[0], bl[2]);
                mma_bf16(acc[mi][pj * 2],     al[mi], bh[0], bh[2]);
                mma_bf16(acc[mi][pj * 2 + 1], ah[mi], bh[1], bh[3]);
                mma_bf16(acc[mi][pj * 2 + 1], ah[mi], bl[1], bl[3]);
                mma_bf16(acc[mi][pj * 2 + 1], al[mi], bh[1], bh[3]);
            }
        }
    }

    // ---- epilogue: scale rows by dinv, store fp32 ----
    #pragma unroll
    for (int mi = 0; mi < 2; mi++) {
        int rl = row0 + wm + mi * 16 + (lane >> 2);
        int rh = rl + 8;
        float dvl = (rl < N_NODES) ? g_dinv[rl] : 0.0f;
        float dvh = (rh < N_NODES) ? g_dinv[rh] : 0.0f;
        #pragma unroll
        for (int nj = 0; nj < 8; nj++) {
            int col = wn + nj * 8 + (lane & 3) * 2;
            if (rl < N_NODES)
                *(float2*)(g_h + (size_t)rl * D + col) =
                    make_float2(dvl * acc[mi][nj][0], dvl * acc[mi][nj][1]);
            if (rh < N_NODES)
                *(float2*)(g_h + (size_t)rh * D + col) =
                    make_float2(dvh * acc[mi][nj][2], dvh * acc[mi][nj][3]);
        }
    }
}

// ---------- 7) gather: out[n] = bias + dinv[n] * sum_{s in bucket(n)} g_h[s] ----------
__global__ void k_gather(const float* __restrict__ bias, float* __restrict__ out) {
    int n = (blockIdx.x * blockDim.x + threadIdx.x) >> 5;
    int lane = threadIdx.x & 31;
    if (n >= N_NODES) return;

    int off = g_offp[n] + g_bsums[n >> 10];
    int cnt = g_cntd[n];
    float dn = g_dinv[n];

    float4 acc = make_float4(0.f, 0.f, 0.f, 0.f);
    int i = 0;
    for (; i + 4 <= cnt; i += 4) {
        int s0 = g_esrc[off + i], s1 = g_esrc[off + i + 1];
        int s2 = g_esrc[off + i + 2], s3 = g_esrc[off + i + 3];
        float4 h0 = *(const float4*)(g_h + (size_t)s0 * D + lane * 4);
        float4 h1 = *(const float4*)(g_h + (size_t)s1 * D + lane * 4);
        float4 h2 = *(const float4*)(g_h + (size_t)s2 * D + lane * 4);
        float4 h3 = *(const float4*)(g_h + (size_t)s3 * D + lane * 4);
        acc.x += (h0.x + h1.x) + (h2.x + h3.x);
        acc.y += (h0.y + h1.y) + (h2.y + h3.y);
        acc.z += (h0.z + h1.z) + (h2.z + h3.z);
        acc.w += (h0.w + h1.w) + (h2.w + h3.w);
    }
    for (; i < cnt; i++) {
        int s0 = g_esrc[off + i];
        float4 h0 = *(const float4*)(g_h + (size_t)s0 * D + lane * 4);
        acc.x += h0.x; acc.y += h0.y; acc.z += h0.z; acc.w += h0.w;
    }

    float4 b = ((const float4*)bias)[lane];
    *(float4*)(out + (size_t)n * D + lane * 4) =
        make_float4(b.x + dn * acc.x, b.y + dn * acc.y, b.z + dn * acc.z, b.w + dn * acc.w);
}

extern "C" void kernel_launch(void* const* d_in, const int* in_sizes, int n_in,
                              void* d_out, int out_size) {
    const float* x    = (const float*)d_in[0];
    const int*   ei   = (const int*)d_in[1];
    const float* w    = (const float*)d_in[2];
    const float* bias = (const float*)d_in[3];
    float*       out  = (float*)d_out;

    // Lazily-created side stream + events for fork-join capture (same DAG every call).
    static cudaStream_t s2 = nullptr;
    static cudaEvent_t ev_fork = nullptr, ev_join = nullptr;
    if (s2 == nullptr) {
        cudaStreamCreateWithFlags(&s2, cudaStreamNonBlocking);
        cudaEventCreateWithFlags(&ev_fork, cudaEventDisableTiming);
        cudaEventCreateWithFlags(&ev_join, cudaEventDisableTiming);
        cudaFuncSetAttribute(k_gemm, cudaFuncAttributeMaxDynamicSharedMemorySize, SM_TOTAL);
    }

    k_zero  <<<(N_NODES + 255) / 256, 256>>>();
    k_count <<<(N_EDGES / 2 + 255) / 256, 256>>>(ei);
    k_dinv  <<<(N_NODES + 255) / 256, 256>>>();

    // fork: gemm (needs only x, w, dinv) runs concurrently with scan+bucket
    cudaEventRecord(ev_fork, 0);
    cudaStreamWaitEvent(s2, ev_fork, 0);
    k_gemm  <<<(N_NODES + 255) / 256, 512, SM_TOTAL, s2>>>(x, w);
    cudaEventRecord(ev_join, s2);

    k_scan1 <<<N_SCAN_BLKS, SCAN_BLK>>>();
    k_scan2 <<<1, SCAN_BLK>>>();
    k_bucket<<<(N_EDGES / 2 + 255) / 256, 256>>>(ei);

    // join: gather needs both branches
    cudaStreamWaitEvent(0, ev_join, 0);
    k_gather<<<(N_NODES * 32 + 255) / 256, 256>>>(bias, out);
}

// round 8
// speedup vs baseline: 1.1537x; 1.1537x over previous
#include <cuda_runtime.h>
#include <cuda_fp16.h>
#include <cstdint>

#define N_NODES 100000
#define N_EDGES 1600000
#define D 128
#define SCAN_BLK 1024
#define N_SCAN_BLKS ((N_NODES + SCAN_BLK - 1) / SCAN_BLK)   // 98

// ---------------- device-global scratch ----------------
__device__ float g_h[(size_t)N_NODES * D];   // dinv[n] * (x @ W)[n]
__device__ float g_dinv[N_NODES];
__device__ int   g_degs[N_NODES];
__device__ int   g_cntd[N_NODES];
__device__ int   g_cur[N_NODES];             // bucket cursors (relative, zero-init)
__device__ int   g_offp[N_NODES];            // per-block exclusive scan partials
__device__ int   g_bsums[SCAN_BLK];          // block sums -> exclusive after scan2
__device__ int   g_esrc[N_EDGES];

__device__ __forceinline__ uint32_t smem_u32(const void* p) {
    uint32_t a;
    asm("{ .reg .u64 t; cvta.to.shared.u64 t, %1; cvt.u32.u64 %0, t; }" : "=r"(a) : "l"(p));
    return a;
}
__device__ __forceinline__ void ldm4(uint32_t* r, uint32_t addr) {
    asm volatile("ldmatrix.sync.aligned.m8n8.x4.shared.b16 {%0,%1,%2,%3}, [%4];"
                 : "=r"(r[0]), "=r"(r[1]), "=r"(r[2]), "=r"(r[3]) : "r"(addr));
}
__device__ __forceinline__ void mma_f16(float* c, const uint32_t* a, uint32_t b0, uint32_t b1) {
    asm volatile("mma.sync.aligned.m16n8k16.row.col.f32.f16.f16.f32 "
                 "{%0,%1,%2,%3}, {%4,%5,%6,%7}, {%8,%9}, {%0,%1,%2,%3};"
                 : "+f"(c[0]), "+f"(c[1]), "+f"(c[2]), "+f"(c[3])
                 : "r"(a[0]), "r"(a[1]), "r"(a[2]), "r"(a[3]), "r"(b0), "r"(b1));
}

// ---------- 1) zero int scratch ----------
__global__ void k_zero() {
    int i = blockIdx.x * blockDim.x + threadIdx.x;
    if (i < N_NODES) { g_degs[i] = 0; g_cntd[i] = 0; g_cur[i] = 0; }
}

// ---------- 2) histograms (2 edges/thread via int2) ----------
__global__ void k_count(const int* __restrict__ ei) {
    int t = blockIdx.x * blockDim.x + threadIdx.x;
    if (t < N_EDGES / 2) {
        int2 s = ((const int2*)ei)[t];
        int2 d = ((const int2*)(ei + N_EDGES))[t];
        atomicAdd(&g_degs[s.x], 1); atomicAdd(&g_degs[s.y], 1);
        atomicAdd(&g_cntd[d.x], 1); atomicAdd(&g_cntd[d.y], 1);
    }
}

// ---------- 3) dinv ----------
__global__ void k_dinv() {
    int i = blockIdx.x * blockDim.x + threadIdx.x;
    if (i < N_NODES) {
        int d = g_degs[i];
        g_dinv[i] = (d > 0) ? rsqrtf((float)d) : 0.0f;
    }
}

// ---------- 4) exclusive scan of g_cntd: offp (in-block) + bsums (cross-block) ----------
__global__ void k_scan1() {
    __shared__ int s[SCAN_BLK];
    int tid = threadIdx.x;
    int i = blockIdx.x * SCAN_BLK + tid;
    int v = (i < N_NODES) ? g_cntd[i] : 0;
    s[tid] = v;
    __syncthreads();
    #pragma unroll
    for (int o = 1; o < SCAN_BLK; o <<= 1) {
        int t = (tid >= o) ? s[tid - o] : 0;
        __syncthreads();
        s[tid] += t;
        __syncthreads();
    }
    if (i < N_NODES) g_offp[i] = s[tid] - v;
    if (tid == SCAN_BLK - 1) g_bsums[blockIdx.x] = s[tid];
}
__global__ void k_scan2() {
    __shared__ int s[SCAN_BLK];
    int tid = threadIdx.x;
    int v = (tid < N_SCAN_BLKS) ? g_bsums[tid] : 0;
    s[tid] = v;
    __syncthreads();
    #pragma unroll
    for (int o = 1; o < SCAN_BLK; o <<= 1) {
        int t = (tid >= o) ? s[tid - o] : 0;
        __syncthreads();
        s[tid] += t;
        __syncthreads();
    }
    if (tid < N_SCAN_BLKS) g_bsums[tid] = s[tid] - v;
}

// ---------- 5) bucket edges by dst (offset computed inline; cursor relative) ----------
__global__ void k_bucket(const int* __restrict__ ei) {
    int t = blockIdx.x * blockDim.x + threadIdx.x;
    if (t < N_EDGES / 2) {
        int2 s = ((const int2*)ei)[t];
        int2 d = ((const int2*)(ei + N_EDGES))[t];
        int p0 = atomicAdd(&g_cur[d.x], 1);
        g_esrc[g_offp[d.x] + g_bsums[d.x >> 10] + p0] = s.x;
        int p1 = atomicAdd(&g_cur[d.y], 1);
        g_esrc[g_offp[d.y] + g_bsums[d.y >> 10] + p1] = s.y;
    }
}

// ---------- 6) HMMA fp16 GEMM: g_h = dinv .* (x @ W) ----------
// CTA: 128 rows x 128 cols, 256 threads (8 warps, 4x2 grid, 32x64 per warp).
// A (x rows, fp16) and B (= W^T [n][k], fp16) in smem, stride 136 halves.
// Single product (fp16 rounding rel-err ~4e-4 << 1e-3 threshold).
#define KS 136                       // smem row stride in halves
#define ROWB (KS * 2)                // 272 bytes
#define OFF_A 0
#define OFF_B (128 * ROWB)           // 34816
#define SM_TOTAL (OFF_B + 128 * ROWB)  // 69632 B -> 2 CTAs/SM

__global__ void __launch_bounds__(256, 2)
k_gemm(const float* __restrict__ x, const float* __restrict__ w) {
    extern __shared__ __align__(16) char smem[];
    const int tid = threadIdx.x;
    const int lane = tid & 31;
    const int wid = tid >> 5;
    const int row0 = blockIdx.x * 128;

    // ---- stage A: 128 rows x 128 cols fp16 ----
    #pragma unroll
    for (int i = tid; i < 2048; i += 256) {
        int r = i >> 4, c8 = i & 15;
        int gr = row0 + r;
        float4 v0 = make_float4(0.f, 0.f, 0.f, 0.f), v1 = v0;
        if (gr < N_NODES) {
            const float4* xp = (const float4*)(x + (size_t)gr * D + c8 * 8);
            v0 = xp[0]; v1 = xp[1];
        }
        __half2 h0 = __floats2half2_rn(v0.x, v0.y);
        __half2 h1 = __floats2half2_rn(v0.z, v0.w);
        __half2 h2 = __floats2half2_rn(v1.x, v1.y);
        __half2 h3 = __floats2half2_rn(v1.z, v1.w);
        *(uint4*)(smem + OFF_A + r * ROWB + c8 * 16) =
            make_uint4(*(uint32_t*)&h0, *(uint32_t*)&h1, *(uint32_t*)&h2, *(uint32_t*)&h3);
    }

    // ---- stage B = W^T: [n][k] fp16 (coalesced w reads, strided smem stores) ----
    #pragma unroll
    for (int i = tid; i < 16384; i += 256) {
        int k = i >> 7, n = i & 127;
        float wv = w[i];                      // w[k*128 + n]
        *(__half*)(smem + OFF_B + n * ROWB + k * 2) = __float2half_rn(wv);
    }
    __syncthreads();

    const uint32_t sbase = smem_u32(smem);
    const int wm = (wid >> 1) * 32;           // warp row base: 0,32,64,96
    const int wn = (wid & 1) * 64;            // warp col base: 0,64

    const uint32_t aoff = sbase + OFF_A + (uint32_t)((wm + (lane & 15)) * ROWB + (lane >> 4) * 16);
    const uint32_t boff = sbase + OFF_B + (uint32_t)((wn + (lane & 15)) * ROWB + (lane >> 4) * 16);

    float acc[2][8][4];
    #pragma unroll
    for (int a = 0; a < 2; a++)
        #pragma unroll
        for (int b = 0; b < 8; b++)
            #pragma unroll
            for (int c = 0; c < 4; c++) acc[a][b][c] = 0.0f;

    #pragma unroll
    for (int ks = 0; ks < 8; ks++) {
        const uint32_t kb = ks * 32;          // 16 halves
        uint32_t am[2][4];
        ldm4(am[0], aoff + kb);
        ldm4(am[1], aoff + 16 * ROWB + kb);
        #pragma unroll
        for (int pj = 0; pj < 4; pj++) {
            uint32_t bm[4];
            ldm4(bm, boff + pj * 16 * ROWB + kb);
            #pragma unroll
            for (int mi = 0; mi < 2; mi++) {
                mma_f16(acc[mi][pj * 2],     am[mi], bm[0], bm[2]);
                mma_f16(acc[mi][pj * 2 + 1], am[mi], bm[1], bm[3]);
            }
        }
    }

    // ---- epilogue: scale rows by dinv, store fp32 ----
    #pragma unroll
    for (int mi = 0; mi < 2; mi++) {
        int rl = row0 + wm + mi * 16 + (lane >> 2);
        int rh = rl + 8;
        float dvl = (rl < N_NODES) ? g_dinv[rl] : 0.0f;
        float dvh = (rh < N_NODES) ? g_dinv[rh] : 0.0f;
        #pragma unroll
        for (int nj = 0; nj < 8; nj++) {
            int col = wn + nj * 8 + (lane & 3) * 2;
            if (rl < N_NODES)
                *(float2*)(g_h + (size_t)rl * D + col) =
                    make_float2(dvl * acc[mi][nj][0], dvl * acc[mi][nj][1]);
            if (rh < N_NODES)
                *(float2*)(g_h + (size_t)rh * D + col) =
                    make_float2(dvh * acc[mi][nj][2], dvh * acc[mi][nj][3]);
        }
    }
}

// ---------- 7) gather: out[n] = bias + dinv[n] * sum_{s in bucket(n)} g_h[s] ----------
__global__ void k_gather(const float* __restrict__ bias, float* __restrict__ out) {
    int n = (blockIdx.x * blockDim.x + threadIdx.x) >> 5;
    int lane = threadIdx.x & 31;
    if (n >= N_NODES) return;

    int off = g_offp[n] + g_bsums[n >> 10];
    int cnt = g_cntd[n];
    float dn = g_dinv[n];

    float4 acc = make_float4(0.f, 0.f, 0.f, 0.f);
    int i = 0;
    for (; i + 4 <= cnt; i += 4) {
        int s0 = g_esrc[off + i], s1 = g_esrc[off + i + 1];
        int s2 = g_esrc[off + i + 2], s3 = g_esrc[off + i + 3];
        float4 h0 = *(const float4*)(g_h + (size_t)s0 * D + lane * 4);
        float4 h1 = *(const float4*)(g_h + (size_t)s1 * D + lane * 4);
        float4 h2 = *(const float4*)(g_h + (size_t)s2 * D + lane * 4);
        float4 h3 = *(const float4*)(g_h + (size_t)s3 * D + lane * 4);
        acc.x += (h0.x + h1.x) + (h2.x + h3.x);
        acc.y += (h0.y + h1.y) + (h2.y + h3.y);
        acc.z += (h0.z + h1.z) + (h2.z + h3.z);
        acc.w += (h0.w + h1.w) + (h2.w + h3.w);
    }
    for (; i < cnt; i++) {
        int s0 = g_esrc[off + i];
        float4 h0 = *(const float4*)(g_h + (size_t)s0 * D + lane * 4);
        acc.x += h0.x; acc.y += h0.y; acc.z += h0.z; acc.w += h0.w;
    }

    float4 b = ((const float4*)bias)[lane];
    *(float4*)(out + (size_t)n * D + lane * 4) =
        make_float4(b.x + dn * acc.x, b.y + dn * acc.y, b.z + dn * acc.z, b.w + dn * acc.w);
}

extern "C" void kernel_launch(void* const* d_in, const int* in_sizes, int n_in,
                              void* d_out, int out_size) {
    const float* x    = (const float*)d_in[0];
    const int*   ei   = (const int*)d_in[1];
    const float* w    = (const float*)d_in[2];
    const float* bias = (const float*)d_in[3];
    float*       out  = (float*)d_out;

    static bool init = false;
    if (!init) {
        cudaFuncSetAttribute(k_gemm, cudaFuncAttributeMaxDynamicSharedMemorySize, SM_TOTAL);
        init = true;
    }

    k_zero  <<<(N_NODES + 255) / 256, 256>>>();
    k_count <<<(N_EDGES / 2 + 255) / 256, 256>>>(ei);
    k_dinv  <<<(N_NODES + 255) / 256, 256>>>();
    k_scan1 <<<N_SCAN_BLKS, SCAN_BLK>>>();
    k_scan2 <<<1, SCAN_BLK>>>();
    k_bucket<<<(N_EDGES / 2 + 255) / 256, 256>>>(ei);
    k_gemm  <<<(N_NODES + 127) / 128, 256, SM_TOTAL>>>(x, w);
    k_gather<<<(N_NODES * 32 + 255) / 256, 256>>>(bias, out);
}

// round 9
// speedup vs baseline: 1.3498x; 1.1700x over previous
#include <cuda_runtime.h>
#include <cuda_fp16.h>
#include <cstdint>

#define N_NODES 100000
#define N_EDGES 1600000
#define D 128
#define SCAN_BLK 1024
#define N_SCAN_BLKS ((N_NODES + SCAN_BLK - 1) / SCAN_BLK)   // 98

// ---------------- device-global scratch ----------------
__device__ __half g_h[(size_t)N_NODES * D]; // fp16: dinv[n] * (x @ W)[n]
__device__ float g_dinv[N_NODES];
__device__ int   g_degs[N_NODES];
__device__ int   g_cntd[N_NODES];
__device__ int   g_cur[N_NODES];             // bucket cursors (relative, zero-init)
__device__ int   g_offp[N_NODES];            // per-block exclusive scan partials
__device__ int   g_bsums[SCAN_BLK];          // block sums -> exclusive after scan2
__device__ int   g_esrc[N_EDGES];

__device__ __forceinline__ uint32_t smem_u32(const void* p) {
    uint32_t a;
    asm("{ .reg .u64 t; cvta.to.shared.u64 t, %1; cvt.u32.u64 %0, t; }" : "=r"(a) : "l"(p));
    return a;
}
__device__ __forceinline__ void ldm4(uint32_t* r, uint32_t addr) {
    asm volatile("ldmatrix.sync.aligned.m8n8.x4.shared.b16 {%0,%1,%2,%3}, [%4];"
                 : "=r"(r[0]), "=r"(r[1]), "=r"(r[2]), "=r"(r[3]) : "r"(addr));
}
__device__ __forceinline__ void mma_f16(float* c, const uint32_t* a, uint32_t b0, uint32_t b1) {
    asm volatile("mma.sync.aligned.m16n8k16.row.col.f32.f16.f16.f32 "
                 "{%0,%1,%2,%3}, {%4,%5,%6,%7}, {%8,%9}, {%0,%1,%2,%3};"
                 : "+f"(c[0]), "+f"(c[1]), "+f"(c[2]), "+f"(c[3])
                 : "r"(a[0]), "r"(a[1]), "r"(a[2]), "r"(a[3]), "r"(b0), "r"(b1));
}
__device__ __forceinline__ void acc_h4(float4& acc, uint2 v) {
    float2 f0 = __half22float2(*(__half2*)&v.x);
    float2 f1 = __half22float2(*(__half2*)&v.y);
    acc.x += f0.x; acc.y += f0.y; acc.z += f1.x; acc.w += f1.y;
}

// ---------- 1) zero int scratch ----------
__global__ void k_zero() {
    int i = blockIdx.x * blockDim.x + threadIdx.x;
    if (i < N_NODES) { g_degs[i] = 0; g_cntd[i] = 0; g_cur[i] = 0; }
}

// ---------- 2) histograms (2 edges/thread via int2) ----------
__global__ void k_count(const int* __restrict__ ei) {
    int t = blockIdx.x * blockDim.x + threadIdx.x;
    if (t < N_EDGES / 2) {
        int2 s = ((const int2*)ei)[t];
        int2 d = ((const int2*)(ei + N_EDGES))[t];
        atomicAdd(&g_degs[s.x], 1); atomicAdd(&g_degs[s.y], 1);
        atomicAdd(&g_cntd[d.x], 1); atomicAdd(&g_cntd[d.y], 1);
    }
}

// ---------- 3) scan1 (+ dinv folded in: same dep, same index space) ----------
__global__ void k_scan1() {
    __shared__ int s[SCAN_BLK];
    int tid = threadIdx.x;
    int i = blockIdx.x * SCAN_BLK + tid;
    if (i < N_NODES) {
        int d = g_degs[i];
        g_dinv[i] = (d > 0) ? rsqrtf((float)d) : 0.0f;
    }
    int v = (i < N_NODES) ? g_cntd[i] : 0;
    s[tid] = v;
    __syncthreads();
    #pragma unroll
    for (int o = 1; o < SCAN_BLK; o <<= 1) {
        int t = (tid >= o) ? s[tid - o] : 0;
        __syncthreads();
        s[tid] += t;
        __syncthreads();
    }
    if (i < N_NODES) g_offp[i] = s[tid] - v;
    if (tid == SCAN_BLK - 1) g_bsums[blockIdx.x] = s[tid];
}
__global__ void k_scan2() {
    __shared__ int s[SCAN_BLK];
    int tid = threadIdx.x;
    int v = (tid < N_SCAN_BLKS) ? g_bsums[tid] : 0;
    s[tid] = v;
    __syncthreads();
    #pragma unroll
    for (int o = 1; o < SCAN_BLK; o <<= 1) {
        int t = (tid >= o) ? s[tid - o] : 0;
        __syncthreads();
        s[tid] += t;
        __syncthreads();
    }
    if (tid < N_SCAN_BLKS) g_bsums[tid] = s[tid] - v;
}

// ---------- 4) bucket edges by dst ----------
__global__ void k_bucket(const int* __restrict__ ei) {
    int t = blockIdx.x * blockDim.x + threadIdx.x;
    if (t < N_EDGES / 2) {
        int2 s = ((const int2*)ei)[t];
        int2 d = ((const int2*)(ei + N_EDGES))[t];
        int p0 = atomicAdd(&g_cur[d.x], 1);
        g_esrc[g_offp[d.x] + g_bsums[d.x >> 10] + p0] = s.x;
        int p1 = atomicAdd(&g_cur[d.y], 1);
        g_esrc[g_offp[d.y] + g_bsums[d.y >> 10] + p1] = s.y;
    }
}

// ---------- 5) HMMA fp16 GEMM: g_h = half(dinv .* (x @ W)) ----------
#define KS 136                       // smem row stride in halves
#define ROWB (KS * 2)                // 272 bytes
#define OFF_A 0
#define OFF_B (128 * ROWB)           // 34816
#define SM_TOTAL (OFF_B + 128 * ROWB)  // 69632 B -> 2 CTAs/SM

__global__ void __launch_bounds__(256, 2)
k_gemm(const float* __restrict__ x, const float* __restrict__ w) {
    extern __shared__ __align__(16) char smem[];
    const int tid = threadIdx.x;
    const int lane = tid & 31;
    const int wid = tid >> 5;
    const int row0 = blockIdx.x * 128;

    // ---- stage A: 128 rows x 128 cols fp16 ----
    #pragma unroll
    for (int i = tid; i < 2048; i += 256) {
        int r = i >> 4, c8 = i & 15;
        int gr = row0 + r;
        float4 v0 = make_float4(0.f, 0.f, 0.f, 0.f), v1 = v0;
        if (gr < N_NODES) {
            const float4* xp = (const float4*)(x + (size_t)gr * D + c8 * 8);
            v0 = xp[0]; v1 = xp[1];
        }
        __half2 h0 = __floats2half2_rn(v0.x, v0.y);
        __half2 h1 = __floats2half2_rn(v0.z, v0.w);
        __half2 h2 = __floats2half2_rn(v1.x, v1.y);
        __half2 h3 = __floats2half2_rn(v1.z, v1.w);
        *(uint4*)(smem + OFF_A + r * ROWB + c8 * 16) =
            make_uint4(*(uint32_t*)&h0, *(uint32_t*)&h1, *(uint32_t*)&h2, *(uint32_t*)&h3);
    }

    // ---- stage B = W^T: [n][k] fp16 ----
    #pragma unroll
    for (int i = tid; i < 16384; i += 256) {
        int k = i >> 7, n = i & 127;
        float wv = w[i];                      // w[k*128 + n], coalesced
        *(__half*)(smem + OFF_B + n * ROWB + k * 2) = __float2half_rn(wv);
    }
    __syncthreads();

    const uint32_t sbase = smem_u32(smem);
    const int wm = (wid >> 1) * 32;
    const int wn = (wid & 1) * 64;

    const uint32_t aoff = sbase + OFF_A + (uint32_t)((wm + (lane & 15)) * ROWB + (lane >> 4) * 16);
    const uint32_t boff = sbase + OFF_B + (uint32_t)((wn + (lane & 15)) * ROWB + (lane >> 4) * 16);

    float acc[2][8][4];
    #pragma unroll
    for (int a = 0; a < 2; a++)
        #pragma unroll
        for (int b = 0; b < 8; b++)
            #pragma unroll
            for (int c = 0; c < 4; c++) acc[a][b][c] = 0.0f;

    #pragma unroll
    for (int ks = 0; ks < 8; ks++) {
        const uint32_t kb = ks * 32;
        uint32_t am[2][4];
        ldm4(am[0], aoff + kb);
        ldm4(am[1], aoff + 16 * ROWB + kb);
        #pragma unroll
        for (int pj = 0; pj < 4; pj++) {
            uint32_t bm[4];
            ldm4(bm, boff + pj * 16 * ROWB + kb);
            #pragma unroll
            for (int mi = 0; mi < 2; mi++) {
                mma_f16(acc[mi][pj * 2],     am[mi], bm[0], bm[2]);
                mma_f16(acc[mi][pj * 2 + 1], am[mi], bm[1], bm[3]);
            }
        }
    }

    // ---- epilogue: scale by dinv, convert to fp16, store half2 ----
    #pragma unroll
    for (int mi = 0; mi < 2; mi++) {
        int rl = row0 + wm + mi * 16 + (lane >> 2);
        int rh = rl + 8;
        float dvl = (rl < N_NODES) ? g_dinv[rl] : 0.0f;
        float dvh = (rh < N_NODES) ? g_dinv[rh] : 0.0f;
        #pragma unroll
        for (int nj = 0; nj < 8; nj++) {
            int col = wn + nj * 8 + (lane & 3) * 2;
            if (rl < N_NODES)
                *(__half2*)(g_h + (size_t)rl * D + col) =
                    __floats2half2_rn(dvl * acc[mi][nj][0], dvl * acc[mi][nj][1]);
            if (rh < N_NODES)
                *(__half2*)(g_h + (size_t)rh * D + col) =
                    __floats2half2_rn(dvh * acc[mi][nj][2], dvh * acc[mi][nj][3]);
        }
    }
}

// ---------- 6) gather: out[n] = bias + dinv[n] * sum_{s in bucket(n)} g_h[s] ----------
__global__ void k_gather(const float* __restrict__ bias, float* __restrict__ out) {
    int n = (blockIdx.x * blockDim.x + threadIdx.x) >> 5;
    int lane = threadIdx.x & 31;
    if (n >= N_NODES) return;

    int off = g_offp[n] + g_bsums[n >> 10];
    int cnt = g_cntd[n];
    float dn = g_dinv[n];

    float4 acc = make_float4(0.f, 0.f, 0.f, 0.f);
    int i = 0;
    for (; i + 4 <= cnt; i += 4) {
        int s0 = g_esrc[off + i], s1 = g_esrc[off + i + 1];
        int s2 = g_esrc[off + i + 2], s3 = g_esrc[off + i + 3];
        uint2 v0 = *((const uint2*)(g_h + (size_t)s0 * D) + lane);
        uint2 v1 = *((const uint2*)(g_h + (size_t)s1 * D) + lane);
        uint2 v2 = *((const uint2*)(g_h + (size_t)s2 * D) + lane);
        uint2 v3 = *((const uint2*)(g_h + (size_t)s3 * D) + lane);
        acc_h4(acc, v0); acc_h4(acc, v1); acc_h4(acc, v2); acc_h4(acc, v3);
    }
    for (; i < cnt; i++) {
        int s0 = g_esrc[off + i];
        uint2 v0 = *((const uint2*)(g_h + (size_t)s0 * D) + lane);
        acc_h4(acc, v0);
    }

    float4 b = ((const float4*)bias)[lane];
    *(float4*)(out + (size_t)n * D + lane * 4) =
        make_float4(b.x + dn * acc.x, b.y + dn * acc.y, b.z + dn * acc.z, b.w + dn * acc.w);
}

extern "C" void kernel_launch(void* const* d_in, const int* in_sizes, int n_in,
                              void* d_out, int out_size) {
    const float* x    = (const float*)d_in[0];
    const int*   ei   = (const int*)d_in[1];
    const float* w    = (const float*)d_in[2];
    const float* bias = (const float*)d_in[3];
    float*       out  = (float*)d_out;

    static bool init = false;
    if (!init) {
        cudaFuncSetAttribute(k_gemm, cudaFuncAttributeMaxDynamicSharedMemorySize, SM_TOTAL);
        init = true;
    }

    k_zero  <<<(N_NODES + 255) / 256, 256>>>();
    k_count <<<(N_EDGES / 2 + 255) / 256, 256>>>(ei);
    k_scan1 <<<N_SCAN_BLKS, SCAN_BLK>>>();
    k_scan2 <<<1, SCAN_BLK>>>();
    k_bucket<<<(N_EDGES / 2 + 255) / 256, 256>>>(ei);
    k_gemm  <<<(N_NODES + 127) / 128, 256, SM_TOTAL>>>(x, w);
    k_gather<<<(N_NODES * 32 + 255) / 256, 256>>>(bias, out);
}

// round 10
// speedup vs baseline: 1.3691x; 1.0143x over previous
#include <cuda_runtime.h>
#include <cuda_fp16.h>
#include <cstdint>

#define N_NODES 100000
#define N_EDGES 1600000
#define D 128
#define SCAN_BLK 1024
#define N_SCAN_BLKS ((N_NODES + SCAN_BLK - 1) / SCAN_BLK)   // 98

// ---------------- device-global scratch ----------------
__device__ __half g_h[(size_t)N_NODES * D]; // fp16: dinv[n] * (x @ W)[n]
__device__ float g_dinv[N_NODES];
__device__ int   g_degs[N_NODES];
__device__ int   g_cntd[N_NODES];
__device__ int   g_cur[N_NODES];             // bucket cursors (relative, zero-init)
__device__ int   g_offp[N_NODES];            // ABSOLUTE exclusive offsets
__device__ volatile int g_aggs[128];         // per-block scan aggregates
__device__ int   g_ready;                    // published-aggregate counter
__device__ int   g_esrc[N_EDGES];

__device__ __forceinline__ uint32_t smem_u32(const void* p) {
    uint32_t a;
    asm("{ .reg .u64 t; cvta.to.shared.u64 t, %1; cvt.u32.u64 %0, t; }" : "=r"(a) : "l"(p));
    return a;
}
__device__ __forceinline__ void ldm4(uint32_t* r, uint32_t addr) {
    asm volatile("ldmatrix.sync.aligned.m8n8.x4.shared.b16 {%0,%1,%2,%3}, [%4];"
                 : "=r"(r[0]), "=r"(r[1]), "=r"(r[2]), "=r"(r[3]) : "r"(addr));
}
__device__ __forceinline__ void mma_f16(float* c, const uint32_t* a, uint32_t b0, uint32_t b1) {
    asm volatile("mma.sync.aligned.m16n8k16.row.col.f32.f16.f16.f32 "
                 "{%0,%1,%2,%3}, {%4,%5,%6,%7}, {%8,%9}, {%0,%1,%2,%3};"
                 : "+f"(c[0]), "+f"(c[1]), "+f"(c[2]), "+f"(c[3])
                 : "r"(a[0]), "r"(a[1]), "r"(a[2]), "r"(a[3]), "r"(b0), "r"(b1));
}
__device__ __forceinline__ void acc_h4(float4& acc, uint2 v) {
    float2 f0 = __half22float2(*(__half2*)&v.x);
    float2 f1 = __half22float2(*(__half2*)&v.y);
    acc.x += f0.x; acc.y += f0.y; acc.z += f1.x; acc.w += f1.y;
}

// ---------- 1) zero int scratch (+ scan ready flag) ----------
__global__ void k_zero() {
    int i = blockIdx.x * blockDim.x + threadIdx.x;
    if (i < N_NODES) { g_degs[i] = 0; g_cntd[i] = 0; g_cur[i] = 0; }
    if (i == 0) g_ready = 0;
}

// ---------- 2) histograms (2 edges/thread via int2) ----------
__global__ void k_count(const int* __restrict__ ei) {
    int t = blockIdx.x * blockDim.x + threadIdx.x;
    if (t < N_EDGES / 2) {
        int2 s = ((const int2*)ei)[t];
        int2 d = ((const int2*)(ei + N_EDGES))[t];
        atomicAdd(&g_degs[s.x], 1); atomicAdd(&g_degs[s.y], 1);
        atomicAdd(&g_cntd[d.x], 1); atomicAdd(&g_cntd[d.y], 1);
    }
}

// ---------- 3) single-pass scan (+ dinv fold) ----------
// 98 blocks, all co-resident (98 < 148 SMs) -> global-flag sync is safe.
__global__ void __launch_bounds__(SCAN_BLK, 1)
k_scan() {
    __shared__ int warp_sums[32];
    __shared__ int s_prefix;
    const int tid = threadIdx.x;
    const int b = blockIdx.x;
    const int i = b * SCAN_BLK + tid;
    const int lane = tid & 31;
    const int wrp = tid >> 5;

    if (i < N_NODES) {
        int d = g_degs[i];
        g_dinv[i] = (d > 0) ? rsqrtf((float)d) : 0.0f;
    }

    int v = (i < N_NODES) ? g_cntd[i] : 0;

    // warp inclusive scan
    int x = v;
    #pragma unroll
    for (int o = 1; o < 32; o <<= 1) {
        int t = __shfl_up_sync(0xFFFFFFFFu, x, o);
        if (lane >= o) x += t;
    }
    if (lane == 31) warp_sums[wrp] = x;
    __syncthreads();
    if (tid < 32) {
        int y = warp_sums[tid];
        #pragma unroll
        for (int o = 1; o < 32; o <<= 1) {
            int t = __shfl_up_sync(0xFFFFFFFFu, y, o);
            if (tid >= o) y += t;
        }
        warp_sums[tid] = y;
    }
    __syncthreads();

    int incl = x + (wrp > 0 ? warp_sums[wrp - 1] : 0);
    int excl = incl - v;
    int block_total = warp_sums[31];

    // publish aggregate, then cross-block prefix via warp 0
    if (tid == 0) {
        g_aggs[b] = block_total;
        __threadfence();
        atomicAdd(&g_ready, 1);
    }
    if (tid < 32) {
        if (lane == 0) {
            while (atomicAdd(&g_ready, 0) < (int)gridDim.x) {}
        }
        __syncwarp();
        __threadfence();
        int p = 0;
        for (int j = lane; j < b; j += 32) p += g_aggs[j];
        #pragma unroll
        for (int o = 16; o; o >>= 1) p += __shfl_down_sync(0xFFFFFFFFu, p, o);
        if (lane == 0) s_prefix = p;
    }
    __syncthreads();

    if (i < N_NODES) g_offp[i] = excl + s_prefix;   // absolute exclusive offset
}

// ---------- 4) bucket edges by dst (absolute offsets) ----------
__global__ void k_bucket(const int* __restrict__ ei) {
    int t = blockIdx.x * blockDim.x + threadIdx.x;
    if (t < N_EDGES / 2) {
        int2 s = ((const int2*)ei)[t];
        int2 d = ((const int2*)(ei + N_EDGES))[t];
        int p0 = atomicAdd(&g_cur[d.x], 1);
        g_esrc[g_offp[d.x] + p0] = s.x;
        int p1 = atomicAdd(&g_cur[d.y], 1);
        g_esrc[g_offp[d.y] + p1] = s.y;
    }
}

// ---------- 5) HMMA fp16 GEMM: g_h = half(dinv .* (x @ W)) ----------
#define KS 136                       // smem row stride in halves
#define ROWB (KS * 2)                // 272 bytes
#define OFF_A 0
#define OFF_B (128 * ROWB)           // 34816
#define SM_TOTAL (OFF_B + 128 * ROWB)  // 69632 B -> 2 CTAs/SM

__global__ void __launch_bounds__(256, 2)
k_gemm(const float* __restrict__ x, const float* __restrict__ w) {
    extern __shared__ __align__(16) char smem[];
    const int tid = threadIdx.x;
    const int lane = tid & 31;
    const int wid = tid >> 5;
    const int row0 = blockIdx.x * 128;

    // ---- stage A: 128 rows x 128 cols fp16 ----
    #pragma unroll
    for (int i = tid; i < 2048; i += 256) {
        int r = i >> 4, c8 = i & 15;
        int gr = row0 + r;
        float4 v0 = make_float4(0.f, 0.f, 0.f, 0.f), v1 = v0;
        if (gr < N_NODES) {
            const float4* xp = (const float4*)(x + (size_t)gr * D + c8 * 8);
            v0 = xp[0]; v1 = xp[1];
        }
        __half2 h0 = __floats2half2_rn(v0.x, v0.y);
        __half2 h1 = __floats2half2_rn(v0.z, v0.w);
        __half2 h2 = __floats2half2_rn(v1.x, v1.y);
        __half2 h3 = __floats2half2_rn(v1.z, v1.w);
        *(uint4*)(smem + OFF_A + r * ROWB + c8 * 16) =
            make_uint4(*(uint32_t*)&h0, *(uint32_t*)&h1, *(uint32_t*)&h2, *(uint32_t*)&h3);
    }

    // ---- stage B = W^T: [n][k] fp16 ----
    #pragma unroll
    for (int i = tid; i < 16384; i += 256) {
        int k = i >> 7, n = i & 127;
        float wv = w[i];                      // w[k*128 + n], coalesced
        *(__half*)(smem + OFF_B + n * ROWB + k * 2) = __float2half_rn(wv);
    }
    __syncthreads();

    const uint32_t sbase = smem_u32(smem);
    const int wm = (wid >> 1) * 32;
    const int wn = (wid & 1) * 64;

    const uint32_t aoff = sbase + OFF_A + (uint32_t)((wm + (lane & 15)) * ROWB + (lane >> 4) * 16);
    const uint32_t boff = sbase + OFF_B + (uint32_t)((wn + (lane & 15)) * ROWB + (lane >> 4) * 16);

    float acc[2][8][4];
    #pragma unroll
    for (int a = 0; a < 2; a++)
        #pragma unroll
        for (int b = 0; b < 8; b++)
            #pragma unroll
            for (int c = 0; c < 4; c++) acc[a][b][c] = 0.0f;

    #pragma unroll
    for (int ks = 0; ks < 8; ks++) {
        const uint32_t kb = ks * 32;
        uint32_t am[2][4];
        ldm4(am[0], aoff + kb);
        ldm4(am[1], aoff + 16 * ROWB + kb);
        #pragma unroll
        for (int pj = 0; pj < 4; pj++) {
            uint32_t bm[4];
            ldm4(bm, boff + pj * 16 * ROWB + kb);
            #pragma unroll
            for (int mi = 0; mi < 2; mi++) {
                mma_f16(acc[mi][pj * 2],     am[mi], bm[0], bm[2]);
                mma_f16(acc[mi][pj * 2 + 1], am[mi], bm[1], bm[3]);
            }
        }
    }

    // ---- epilogue: scale by dinv, convert to fp16, store half2 ----
    #pragma unroll
    for (int mi = 0; mi < 2; mi++) {
        int rl = row0 + wm + mi * 16 + (lane >> 2);
        int rh = rl + 8;
        float dvl = (rl < N_NODES) ? g_dinv[rl] : 0.0f;
        float dvh = (rh < N_NODES) ? g_dinv[rh] : 0.0f;
        #pragma unroll
        for (int nj = 0; nj < 8; nj++) {
            int col = wn + nj * 8 + (lane & 3) * 2;
            if (rl < N_NODES)
                *(__half2*)(g_h + (size_t)rl * D + col) =
                    __floats2half2_rn(dvl * acc[mi][nj][0], dvl * acc[mi][nj][1]);
            if (rh < N_NODES)
                *(__half2*)(g_h + (size_t)rh * D + col) =
                    __floats2half2_rn(dvh * acc[mi][nj][2], dvh * acc[mi][nj][3]);
        }
    }
}

// ---------- 6) gather: out[n] = bias + dinv[n] * sum_{s in bucket(n)} g_h[s] ----------
__global__ void k_gather(const float* __restrict__ bias, float* __restrict__ out) {
    int n = (blockIdx.x * blockDim.x + threadIdx.x) >> 5;
    int lane = threadIdx.x & 31;
    if (n >= N_NODES) return;

    int off = g_offp[n];
    int cnt = g_cur[n];          // cursor == bucket size after k_bucket
    float dn = g_dinv[n];

    float4 acc = make_float4(0.f, 0.f, 0.f, 0.f);
    int i = 0;
    for (; i + 4 <= cnt; i += 4) {
        int s0 = g_esrc[off + i], s1 = g_esrc[off + i + 1];
        int s2 = g_esrc[off + i + 2], s3 = g_esrc[off + i + 3];
        uint2 v0 = *((const uint2*)(g_h + (size_t)s0 * D) + lane);
        uint2 v1 = *((const uint2*)(g_h + (size_t)s1 * D) + lane);
        uint2 v2 = *((const uint2*)(g_h + (size_t)s2 * D) + lane);
        uint2 v3 = *((const uint2*)(g_h + (size_t)s3 * D) + lane);
        acc_h4(acc, v0); acc_h4(acc, v1); acc_h4(acc, v2); acc_h4(acc, v3);
    }
    for (; i < cnt; i++) {
        int s0 = g_esrc[off + i];
        uint2 v0 = *((const uint2*)(g_h + (size_t)s0 * D) + lane);
        acc_h4(acc, v0);
    }

    float4 b = ((const float4*)bias)[lane];
    *(float4*)(out + (size_t)n * D + lane * 4) =
        make_float4(b.x + dn * acc.x, b.y + dn * acc.y, b.z + dn * acc.z, b.w + dn * acc.w);
}

extern "C" void kernel_launch(void* const* d_in, const int* in_sizes, int n_in,
                              void* d_out, int out_size) {
    const float* x    = (const float*)d_in[0];
    const int*   ei   = (const int*)d_in[1];
    const float* w    = (const float*)d_in[2];
    const float* bias = (const float*)d_in[3];
    float*       out  = (float*)d_out;

    static bool init = false;
    if (!init) {
        cudaFuncSetAttribute(k_gemm, cudaFuncAttributeMaxDynamicSharedMemorySize, SM_TOTAL);
        init = true;
    }

    k_zero  <<<(N_NODES + 255) / 256, 256>>>();
    k_count <<<(N_EDGES / 2 + 255) / 256, 256>>>(ei);
    k_scan  <<<N_SCAN_BLKS, SCAN_BLK>>>();
    k_bucket<<<(N_EDGES / 2 + 255) / 256, 256>>>(ei);
    k_gemm  <<<(N_NODES + 127) / 128, 256, SM_TOTAL>>>(x, w);
    k_gather<<<(N_NODES * 32 + 255) / 256, 256>>>(bias, out);
}